// round 12
// baseline (speedup 1.0000x reference)
#include <cuda_runtime.h>

typedef unsigned long long ull;

#define C_ 64
#define S_ 32
#define D_ 32
#define HW_ 4096
#define DHW_ 131072
#define NCH 96

__device__ float g_kqv[4 * NCH * DHW_];   /* [b][ch][dhw], ch: 0-31 k, 32-63 q, 64-95 v */

__constant__ float cBcat[NCH];            /* bk | bq | bv */
__constant__ float cWO[C_*S_];
__constant__ float cBO[C_];

__device__ __forceinline__ ull f2fma(ull a, ull b, ull c) {
    ull d; asm("fma.rn.f32x2 %0,%1,%2,%3;" : "=l"(d) : "l"(a), "l"(b), "l"(c)); return d;
}
__device__ __forceinline__ ull f2add(ull a, ull b) {
    ull d; asm("add.rn.f32x2 %0,%1,%2;" : "=l"(d) : "l"(a), "l"(b)); return d;
}
__device__ __forceinline__ ull f2dup(float x) {
    ull d; asm("mov.b64 %0,{%1,%1};" : "=l"(d) : "f"(x)); return d;
}
__device__ __forceinline__ ull f2pack(float x, float y) {
    ull d; asm("mov.b64 %0,{%1,%2};" : "=l"(d) : "f"(x), "f"(y)); return d;
}
__device__ __forceinline__ float2 f2unpack(ull a) {
    float lo, hi; asm("mov.b64 {%0,%1},%2;" : "=f"(lo), "=f"(hi) : "l"(a));
    return make_float2(lo, hi);
}
__device__ __forceinline__ float hadd(ull a) {
    const float2 p = f2unpack(a); return p.x + p.y;
}

/* ================= Kernel 1: KQV projection GEMM =================
   g_kqv[b][96][dhw] = Wcat[96,64] @ x[b][64,dhw] + bias.
   CTA 192 thr, tile [96 x 128 cols], thread 8ch x 8col (8:1 fma:lds). */
#define K1T 192
#define XS_STR 132
#define WT_STR 100
#define K1_SMEM_FLOATS (64*XS_STR + 64*WT_STR)   /* 14848 = 59392 B */

__global__ void __launch_bounds__(192, 3)
kqv_gemm_kernel(const float* __restrict__ x,
                const float* __restrict__ Wk,
                const float* __restrict__ Wq,
                const float* __restrict__ Wv)
{
    extern __shared__ float sm[];
    float* XS = sm;                   /* [k=64][132] */
    float* WT = sm + 64*XS_STR;       /* [k=64][100], ch-major */

    const int tid  = threadIdx.x;
    const int bx   = blockIdx.x;
    const int tile = bx & 1023;
    const int b    = bx >> 10;
    const int colbase = tile * 128;

    /* stage weights transposed: WT[c][ch] */
    for (int i = tid; i < S_*C_; i += K1T) {
        const int c = i & 63, s = i >> 6;
        WT[c*WT_STR + s]      = Wk[i];
        WT[c*WT_STR + 32 + s] = Wq[i];
        WT[c*WT_STR + 64 + s] = Wv[i];
    }
    /* stage X[64][128] (coalesced float4) */
    for (int f = tid; f < 64*32; f += K1T) {
        const int c = f >> 5;
        const int col4 = (f & 31) * 4;
        *(float4*)&XS[c*XS_STR + col4] =
            *(const float4*)&x[(size_t)(b*64 + c)*DHW_ + colbase + col4];
    }
    __syncthreads();

    const int tm = tid / 16;          /* 0..11: ch-group of 8 */
    const int tc = tid % 16;          /* 0..15: col-group of 8 */
    const int ch0  = tm * 8;
    const int col0 = tc * 8;

    ull acc[8][4];
#pragma unroll
    for (int m = 0; m < 8; m++)
#pragma unroll
        for (int n = 0; n < 4; n++) acc[m][n] = 0ULL;

#pragma unroll 4
    for (int k = 0; k < 64; k++) {
        const ulonglong2 wa = *(const ulonglong2*)&WT[k*WT_STR + ch0];
        const ulonglong2 wb = *(const ulonglong2*)&WT[k*WT_STR + ch0 + 4];
        const ulonglong2 xa = *(const ulonglong2*)&XS[k*XS_STR + col0];
        const ulonglong2 xb = *(const ulonglong2*)&XS[k*XS_STR + col0 + 4];
        const float2 w01 = f2unpack(wa.x);
        const float2 w23 = f2unpack(wa.y);
        const float2 w45 = f2unpack(wb.x);
        const float2 w67 = f2unpack(wb.y);
        ull wd[8];
        wd[0] = f2dup(w01.x); wd[1] = f2dup(w01.y);
        wd[2] = f2dup(w23.x); wd[3] = f2dup(w23.y);
        wd[4] = f2dup(w45.x); wd[5] = f2dup(w45.y);
        wd[6] = f2dup(w67.x); wd[7] = f2dup(w67.y);
#pragma unroll
        for (int m = 0; m < 8; m++) {
            acc[m][0] = f2fma(wd[m], xa.x, acc[m][0]);
            acc[m][1] = f2fma(wd[m], xa.y, acc[m][1]);
            acc[m][2] = f2fma(wd[m], xb.x, acc[m][2]);
            acc[m][3] = f2fma(wd[m], xb.y, acc[m][3]);
        }
    }

    /* epilogue: + bias, coalesced STG */
#pragma unroll
    for (int m = 0; m < 8; m++) {
        const ull bb = f2dup(cBcat[ch0 + m]);
        float* dst = &g_kqv[(size_t)(b*NCH + ch0 + m)*DHW_ + colbase + col0];
        ulonglong2 r0, r1;
        r0.x = f2add(acc[m][0], bb); r0.y = f2add(acc[m][1], bb);
        r1.x = f2add(acc[m][2], bb); r1.y = f2add(acc[m][3], bb);
        *(ulonglong2*)dst       = r0;
        *(ulonglong2*)(dst + 4) = r1;
    }
}

/* ================= Kernel 2: attention + outproj + residual =================
   TW=8 pixels per block, 256 thr, warp = pixel, lane = d (= j). */
#define RA_WARP 2176      /* per-warp kT(1088 @0) + qT(1088 @1088), stride 34 */
#define RB_BASE 17408     /* vS region: per-warp 1088, stride 68 */
#define K2_SMEM_FLOATS (RB_BASE + 8*1088)   /* 26112 = 104448 B */
#define OT_STR 33         /* otile rows (c*8+w), overlays region A */

__global__ void __launch_bounds__(256, 2)
attn_kernel(const float* __restrict__ x, float* __restrict__ out)
{
    extern __shared__ float sm[];
    const int tid = threadIdx.x;
    const int bx  = blockIdx.x;
    const int wt  = bx & 7;
    const int h   = (bx >> 3) & 63;
    const int b   = bx >> 9;
    const int hw0 = h*64 + wt*8;

    /* ---- stage kqv slab: 96ch x 32d x 8w, lane = d (32B full sectors) ---- */
#pragma unroll 4
    for (int it = 0; it < 12; it++) {
        const int row = tid + it*256;
        const int d  = row & 31;
        const int ch = row >> 5;
        const float* src = &g_kqv[((size_t)(b*NCH + ch)*32 + d)*4096 + hw0];
        const float4 va = *(const float4*)src;
        const float4 vb = *(const float4*)(src + 4);
        const float v[8] = {va.x, va.y, va.z, va.w, vb.x, vb.y, vb.z, vb.w};
        if (ch < 32) {                 /* k -> kT[d][s], stride 34 */
#pragma unroll
            for (int w = 0; w < 8; w++) sm[w*RA_WARP + d*34 + ch] = v[w];
        } else if (ch < 64) {          /* q -> qT[d][s] */
            const int s = ch - 32;
#pragma unroll
            for (int w = 0; w < 8; w++) sm[w*RA_WARP + 1088 + d*34 + s] = v[w];
        } else {                       /* v -> vS[sp][2i+p], stride 68 */
            const int s = ch - 64;
            const int off = (s >> 1)*68 + (s & 1);
#pragma unroll
            for (int w = 0; w < 8; w++) sm[RB_BASE + w*1088 + off + 2*d] = v[w];
        }
    }
    __syncthreads();

    const int warp = tid >> 5;    /* pixel */
    const int lane = tid & 31;    /* d (and j) */
    const float* kT = sm + warp*RA_WARP;
    const float* qT = kT + 1088;
    const float* vS = sm + RB_BASE + warp*1088;

    /* q2[t] = (q[2t][j], q[2t+1][j]) */
    ull q2[16];
#pragma unroll
    for (int t = 0; t < 16; t++) q2[t] = *(const ull*)&qT[lane*34 + 2*t];

    /* scores a[i] */
    float a[D_];
#pragma unroll
    for (int i = 0; i < D_; i++) {
        ull a0 = 0ULL, a1 = 0ULL;
#pragma unroll
        for (int t = 0; t < 16; t += 2) {
            a0 = f2fma(*(const ull*)&kT[i*34 + 2*t],     q2[t],   a0);
            a1 = f2fma(*(const ull*)&kT[i*34 + 2*t + 2], q2[t+1], a1);
        }
        a[i] = hadd(f2add(a0, a1)) * 0.17677669529663687f;   /* 1/sqrt(32) */
    }

    /* softmax over i */
    {
        float m = a[0];
#pragma unroll
        for (int i = 1; i < D_; i++) m = fmaxf(m, a[i]);
        float ssum = 0.f;
#pragma unroll
        for (int i = 0; i < D_; i++) { a[i] = __expf(a[i] - m); ssum += a[i]; }
        const float inv = 1.0f / ssum;
#pragma unroll
        for (int i = 0; i < D_; i++) a[i] *= inv;
    }

    /* o2[sp] = sum_i vS(sp,i) * a[i] */
    ull o2[16];
#pragma unroll
    for (int sp = 0; sp < 16; sp++) o2[sp] = 0ULL;
#pragma unroll
    for (int t = 0; t < 16; t++) {
        const ull d0 = f2dup(a[2*t]);
        const ull d1 = f2dup(a[2*t+1]);
#pragma unroll
        for (int sp = 0; sp < 16; sp++) {
            const ulonglong2 vv = *(const ulonglong2*)&vS[sp*68 + 4*t];
            o2[sp] = f2fma(vv.x, d0, o2[sp]);
            o2[sp] = f2fma(vv.y, d1, o2[sp]);
        }
    }
    __syncthreads();   /* all kT/qT reads done -> region A becomes otile */

    /* outproj (LDC Wo) -> otile[(c*8+warp)][lane] */
#pragma unroll 8
    for (int c = 0; c < C_; c++) {
        ull a0 = 0ULL, a1 = 0ULL;
#pragma unroll
        for (int t = 0; t < 8; t++) {
            const ulonglong2 ww = *(const ulonglong2*)&cWO[c*S_ + 4*t];
            a0 = f2fma(ww.x, o2[2*t],   a0);
            a1 = f2fma(ww.y, o2[2*t+1], a1);
        }
        sm[(c*8 + warp)*OT_STR + lane] = hadd(f2add(a0, a1)) + cBO[c];
    }
    __syncthreads();

    /* final: out = otile + residual (x re-read from global) */
#pragma unroll 2
    for (int e = tid; e < C_*D_; e += 256) {
        const int d = e & 31;
        const int c = e >> 5;
        const float* xs = &x[((size_t)(b*64 + c)*32 + d)*4096 + hw0];
        const float4 xa = *(const float4*)xs;
        const float4 xb = *(const float4*)(xs + 4);
        float4 ra, rb;
        ra.x = xa.x + sm[(c*8 + 0)*OT_STR + d];
        ra.y = xa.y + sm[(c*8 + 1)*OT_STR + d];
        ra.z = xa.z + sm[(c*8 + 2)*OT_STR + d];
        ra.w = xa.w + sm[(c*8 + 3)*OT_STR + d];
        rb.x = xb.x + sm[(c*8 + 4)*OT_STR + d];
        rb.y = xb.y + sm[(c*8 + 5)*OT_STR + d];
        rb.z = xb.z + sm[(c*8 + 6)*OT_STR + d];
        rb.w = xb.w + sm[(c*8 + 7)*OT_STR + d];
        float* dst = &out[((size_t)(b*64 + c)*32 + d)*4096 + hw0];
        *(float4*)dst       = ra;
        *(float4*)(dst + 4) = rb;
    }
}

extern "C" void kernel_launch(void* const* d_in, const int* in_sizes, int n_in,
                              void* d_out, int out_size)
{
    const float* x  = (const float*)d_in[0];
    const float* Wk = (const float*)d_in[1];
    const float* Wq = (const float*)d_in[3];
    const float* Wv = (const float*)d_in[5];
    float* out = (float*)d_out;

    cudaMemcpyToSymbolAsync(cBcat, d_in[2], S_*sizeof(float),  0,               cudaMemcpyDeviceToDevice, 0);
    cudaMemcpyToSymbolAsync(cBcat, d_in[4], S_*sizeof(float), 32*sizeof(float), cudaMemcpyDeviceToDevice, 0);
    cudaMemcpyToSymbolAsync(cBcat, d_in[6], S_*sizeof(float), 64*sizeof(float), cudaMemcpyDeviceToDevice, 0);
    cudaMemcpyToSymbolAsync(cWO,  d_in[7], C_*S_*sizeof(float), 0, cudaMemcpyDeviceToDevice, 0);
    cudaMemcpyToSymbolAsync(cBO,  d_in[8], C_*sizeof(float),    0, cudaMemcpyDeviceToDevice, 0);

    const size_t s1 = (size_t)K1_SMEM_FLOATS * sizeof(float);
    const size_t s2 = (size_t)K2_SMEM_FLOATS * sizeof(float);
    cudaFuncSetAttribute(kqv_gemm_kernel, cudaFuncAttributeMaxDynamicSharedMemorySize, (int)s1);
    cudaFuncSetAttribute(attn_kernel,     cudaFuncAttributeMaxDynamicSharedMemorySize, (int)s2);

    kqv_gemm_kernel<<<4096, 192, s1>>>(x, Wk, Wq, Wv);
    attn_kernel<<<2048, 256, s2>>>(x, out);
}

// round 13
// speedup vs baseline: 1.0085x; 1.0085x over previous
#include <cuda_runtime.h>

typedef unsigned long long ull;

#define C_ 64
#define D_ 32
#define S_ 32
#define HW_ 4096
#define DHW_ 131072

/* smem layout (floats) */
#define OFF_KT 0              /* kT[w][d][s]: per-pixel 1156, stride 36 */
#define KTP 1156
#define OFF_XS 9248           /* x chunk [8c][384], addr = c*384 + 12*d + w */
#define OFF_WT 12320          /* Wcat^T [c=64][100]: ch 0-31 k, 32-63 q, 64-95 v */
#define OFF_VS 18720          /* vS[w][sp][2i]: per-pixel 1092, stride 68 */
#define SMEM_FLOATS (OFF_VS + 8*1092)   /* 27456 fl = 109824 B -> 2 CTAs/SM */
/* otile overlays [0, 16896): (c*8+w)*33 + d */

__constant__ float cBK[S_];
__constant__ float cBQ[S_];
__constant__ float cBV[S_];
__constant__ float cWO[C_*S_];
__constant__ float cBO[C_];

__device__ __forceinline__ ull f2fma(ull a, ull b, ull c) {
    ull d; asm("fma.rn.f32x2 %0,%1,%2,%3;" : "=l"(d) : "l"(a), "l"(b), "l"(c)); return d;
}
__device__ __forceinline__ ull f2add(ull a, ull b) {
    ull d; asm("add.rn.f32x2 %0,%1,%2;" : "=l"(d) : "l"(a), "l"(b)); return d;
}
__device__ __forceinline__ ull f2dup(float x) {
    ull d; asm("mov.b64 %0,{%1,%1};" : "=l"(d) : "f"(x)); return d;
}
__device__ __forceinline__ float2 f2unpack(ull a) {
    float lo, hi; asm("mov.b64 {%0,%1},%2;" : "=f"(lo), "=f"(hi) : "l"(a));
    return make_float2(lo, hi);
}
__device__ __forceinline__ float hadd(ull a) {
    const float2 p = f2unpack(a); return p.x + p.y;
}

__global__ void __launch_bounds__(256, 2)
attn_fused_kernel(const float* __restrict__ x,
                  const float* __restrict__ Wk,
                  const float* __restrict__ Wq,
                  const float* __restrict__ Wv,
                  float* __restrict__ out)
{
    extern __shared__ float sm[];
    const int tid  = threadIdx.x;
    const int warp = tid >> 5;     /* GEMM: ch-group; attention: pixel w */
    const int lane = tid & 31;     /* GEMM: col d-group; attention: d = j */
    const int bx  = blockIdx.x;
    const int wt  = bx & 7;
    const int h   = (bx >> 3) & 63;
    const int b   = bx >> 9;
    const int hw0 = h*64 + wt*8;

    /* ---- stage Wcat^T [c][ch]: ch = s(k) | 32+s(q) | 64+s(v) ---- */
    for (int i = tid; i < S_*C_; i += 256) {
        const int c = i & 63, s = i >> 6;
        sm[OFF_WT + c*100 + s]      = Wk[i];
        sm[OFF_WT + c*100 + 32 + s] = Wq[i];
        sm[OFF_WT + c*100 + 64 + s] = Wv[i];
    }

    /* ---- GEMM accumulators ---- */
    ull acc[32];                        /* [chpair 4][w 8], k or v per warp */
#pragma unroll
    for (int i = 0; i < 32; i++) acc[i] = 0ULL;
    ull q2[16];                         /* own attention column's q, s-pairs */
#pragma unroll
    for (int t = 0; t < 16; t++) q2[t] = *(const ull*)&cBQ[2*t];

    const int ch0 = (warp & 3) * 8;     /* warps 0-3: k ch0; 4-7: v ch0 */

    /* ---- mainloop: 8 chunks of 8 channels ---- */
    for (int kc = 0; kc < 8; kc++) {
        /* stage chunk: thread = row (c_loc=warp, d=lane), 8 w contiguous */
        {
            const float* src = x + (size_t)((b*64 + kc*8 + warp)*32 + lane)*4096 + hw0;
            const float4 va = *(const float4*)src;
            const float4 vb = *(const float4*)(src + 4);
            float* dst = sm + OFF_XS + warp*384 + 12*lane;
            *(float4*)dst       = va;
            *(float4*)(dst + 4) = vb;
        }
        __syncthreads();
#pragma unroll
        for (int cl = 0; cl < 8; cl++) {
            const float* xrow = sm + OFF_XS + cl*384;
            const float* wrow = sm + OFF_WT + (kc*8 + cl)*100;
            /* x for own 8 cols (d = lane, w = 0..7), conflict-free skew-12 */
            const ulonglong2 xa = *(const ulonglong2*)&xrow[12*lane];
            const ulonglong2 xb = *(const ulonglong2*)&xrow[12*lane + 4];
            ull xd[8];
            { float2 p;
              p = f2unpack(xa.x); xd[0]=f2dup(p.x); xd[1]=f2dup(p.y);
              p = f2unpack(xa.y); xd[2]=f2dup(p.x); xd[3]=f2dup(p.y);
              p = f2unpack(xb.x); xd[4]=f2dup(p.x); xd[5]=f2dup(p.y);
              p = f2unpack(xb.y); xd[6]=f2dup(p.x); xd[7]=f2dup(p.y); }
            /* k/v weights: 4 ch-pairs (broadcast) */
            const int base = (warp < 4) ? ch0 : (64 + ch0);
            const ulonglong2 wa = *(const ulonglong2*)&wrow[base];
            const ulonglong2 wb = *(const ulonglong2*)&wrow[base + 4];
#pragma unroll
            for (int w8 = 0; w8 < 8; w8++) {
                acc[     w8] = f2fma(wa.x, xd[w8], acc[     w8]);
                acc[ 8 + w8] = f2fma(wa.y, xd[w8], acc[ 8 + w8]);
                acc[16 + w8] = f2fma(wb.x, xd[w8], acc[16 + w8]);
                acc[24 + w8] = f2fma(wb.y, xd[w8], acc[24 + w8]);
            }
            /* q for own attention column (w=warp, d=lane) */
            const ull qx = f2dup(xrow[12*lane + warp]);
#pragma unroll
            for (int t = 0; t < 8; t++) {
                const ulonglong2 qw = *(const ulonglong2*)&wrow[32 + 4*t];
                q2[2*t]   = f2fma(qw.x, qx, q2[2*t]);
                q2[2*t+1] = f2fma(qw.y, qx, q2[2*t+1]);
            }
        }
        __syncthreads();
    }

    /* ---- GEMM epilogue: scatter k -> kT, v -> vS (cross-warp regions) ---- */
    if (warp < 4) {
#pragma unroll
        for (int cp = 0; cp < 4; cp++) {
            const int s0 = warp*8 + 2*cp;
            const float b0 = cBK[s0], b1 = cBK[s0+1];
#pragma unroll
            for (int w8 = 0; w8 < 8; w8++) {
                const float2 v = f2unpack(acc[cp*8 + w8]);
                sm[OFF_KT + w8*KTP + lane*36 + s0]     = v.x + b0;
                sm[OFF_KT + w8*KTP + lane*36 + s0 + 1] = v.y + b1;
            }
        }
    } else {
#pragma unroll
        for (int cp = 0; cp < 4; cp++) {
            const int s0 = (warp-4)*8 + 2*cp;
            const float b0 = cBV[s0], b1 = cBV[s0+1];
            const int spg = s0 >> 1;
#pragma unroll
            for (int w8 = 0; w8 < 8; w8++) {
                const float2 v = f2unpack(acc[cp*8 + w8]);
                sm[OFF_VS + w8*1092 + spg*68 + 2*lane]     = v.x + b0;
                sm[OFF_VS + w8*1092 + spg*68 + 2*lane + 1] = v.y + b1;
            }
        }
    }
    __syncthreads();

    /* ---- scores a[i], this warp = pixel, lane = column j ---- */
    const float* kT = sm + OFF_KT + warp*KTP;
    float a[D_];
#pragma unroll
    for (int i = 0; i < D_; i++) {
        ull a0 = 0ULL, a1 = 0ULL;
#pragma unroll
        for (int t = 0; t < 8; t++) {
            const ulonglong2 kk = *(const ulonglong2*)&kT[i*36 + 4*t];
            a0 = f2fma(kk.x, q2[2*t],   a0);
            a1 = f2fma(kk.y, q2[2*t+1], a1);
        }
        a[i] = hadd(f2add(a0, a1)) * 0.17677669529663687f;   /* 1/sqrt(32) */
    }

    /* ---- softmax over i ---- */
    {
        float m = a[0];
#pragma unroll
        for (int i = 1; i < D_; i++) m = fmaxf(m, a[i]);
        float ssum = 0.f;
#pragma unroll
        for (int i = 0; i < D_; i++) { a[i] = __expf(a[i] - m); ssum += a[i]; }
        const float inv = 1.0f / ssum;
#pragma unroll
        for (int i = 0; i < D_; i++) a[i] *= inv;
    }

    /* ---- o2[sp] = sum_i vS(sp,i) * a[i] ---- */
    const float* vS = sm + OFF_VS + warp*1092;
    ull o2[16];
#pragma unroll
    for (int sp = 0; sp < 16; sp++) o2[sp] = 0ULL;
#pragma unroll
    for (int t = 0; t < 16; t++) {
        const ull d0 = f2dup(a[2*t]);
        const ull d1 = f2dup(a[2*t+1]);
#pragma unroll
        for (int sp = 0; sp < 16; sp++) {
            const ulonglong2 vv = *(const ulonglong2*)&vS[sp*68 + 4*t];
            o2[sp] = f2fma(vv.x, d0, o2[sp]);
            o2[sp] = f2fma(vv.y, d1, o2[sp]);
        }
    }
    __syncthreads();   /* all scores/o reads done -> region 0 becomes otile */

    /* ---- outproj (LDC Wo) -> otile[(c*8+warp)*33 + lane] ---- */
#pragma unroll 8
    for (int c = 0; c < C_; c++) {
        ull a0 = 0ULL, a1 = 0ULL;
#pragma unroll
        for (int t = 0; t < 8; t++) {
            const ulonglong2 ww = *(const ulonglong2*)&cWO[c*S_ + 4*t];
            a0 = f2fma(ww.x, o2[2*t],   a0);
            a1 = f2fma(ww.y, o2[2*t+1], a1);
        }
        sm[(c*8 + warp)*33 + lane] = hadd(f2add(a0, a1)) + cBO[c];
    }
    __syncthreads();

    /* ---- final: out = otile + residual (x re-read from global) ---- */
#pragma unroll
    for (int it = 0; it < 8; it++) {
        const int row = tid + it*256;
        const int d = row & 31;
        const int c = row >> 5;
        const float* xs = x + (size_t)((b*64 + c)*32 + d)*4096 + hw0;
        const float4 xa = *(const float4*)xs;
        const float4 xb = *(const float4*)(xs + 4);
        float4 ra, rb;
        ra.x = xa.x + sm[(c*8 + 0)*33 + d];
        ra.y = xa.y + sm[(c*8 + 1)*33 + d];
        ra.z = xa.z + sm[(c*8 + 2)*33 + d];
        ra.w = xa.w + sm[(c*8 + 3)*33 + d];
        rb.x = xb.x + sm[(c*8 + 4)*33 + d];
        rb.y = xb.y + sm[(c*8 + 5)*33 + d];
        rb.z = xb.z + sm[(c*8 + 6)*33 + d];
        rb.w = xb.w + sm[(c*8 + 7)*33 + d];
        float* dst = out + (size_t)((b*64 + c)*32 + d)*4096 + hw0;
        *(float4*)dst       = ra;
        *(float4*)(dst + 4) = rb;
    }
}

extern "C" void kernel_launch(void* const* d_in, const int* in_sizes, int n_in,
                              void* d_out, int out_size)
{
    const float* x  = (const float*)d_in[0];
    const float* Wk = (const float*)d_in[1];
    const float* Wq = (const float*)d_in[3];
    const float* Wv = (const float*)d_in[5];
    float* out = (float*)d_out;

    cudaMemcpyToSymbolAsync(cBK, d_in[2], S_*sizeof(float),    0, cudaMemcpyDeviceToDevice, 0);
    cudaMemcpyToSymbolAsync(cBQ, d_in[4], S_*sizeof(float),    0, cudaMemcpyDeviceToDevice, 0);
    cudaMemcpyToSymbolAsync(cBV, d_in[6], S_*sizeof(float),    0, cudaMemcpyDeviceToDevice, 0);
    cudaMemcpyToSymbolAsync(cWO, d_in[7], C_*S_*sizeof(float), 0, cudaMemcpyDeviceToDevice, 0);
    cudaMemcpyToSymbolAsync(cBO, d_in[8], C_*sizeof(float),    0, cudaMemcpyDeviceToDevice, 0);

    const size_t smem_bytes = (size_t)SMEM_FLOATS * sizeof(float);
    cudaFuncSetAttribute(attn_fused_kernel,
                         cudaFuncAttributeMaxDynamicSharedMemorySize,
                         (int)smem_bytes);

    const int grid = 4 * 64 * 8;   /* B * H * (W/8) = 2048 */
    attn_fused_kernel<<<grid, 256, smem_bytes>>>(x, Wk, Wq, Wv, out);
}

// round 15
// speedup vs baseline: 1.0254x; 1.0168x over previous
#include <cuda_runtime.h>

typedef unsigned long long ull;

#define TW 4
#define C_ 64
#define D_ 32
#define S_ 32
#define SP_ 16
#define HW_ 4096
#define DHW_ 131072

#define XROW 68          /* x-tile: [w][d][c-contig] */
#define PIXST 2184       /* 32*68 + 8 */
#define OROW 35          /* otile [(c*4+w)][d] — overlays x-tile region */
#define OFF_R1 0
#define N_R1 8960        /* max(x 4*2184=8736, otile 256*35=8960) */
#define OFF_SC N_R1
#define SCW 2240         /* per-warp: kT 32x36=1152 @0, vS 16x68=1088 @1152 */
#define SMEM_FLOATS (OFF_SC + 4*SCW)   /* 17920 floats = 71680 B -> 3 CTAs/SM */

__constant__ float cWK[S_*C_];
__constant__ float cWQ[S_*C_];
__constant__ float cWV[S_*C_];
__constant__ float cWO[C_*S_];
__constant__ float cBK[S_];
__constant__ float cBQ[S_];
__constant__ float cBV[S_];
__constant__ float cBO[C_];

__device__ __forceinline__ ull f2fma(ull a, ull b, ull c) {
    ull d; asm("fma.rn.f32x2 %0,%1,%2,%3;" : "=l"(d) : "l"(a), "l"(b), "l"(c)); return d;
}
__device__ __forceinline__ ull f2add(ull a, ull b) {
    ull d; asm("add.rn.f32x2 %0,%1,%2;" : "=l"(d) : "l"(a), "l"(b)); return d;
}
__device__ __forceinline__ ull f2dup(float x) {
    ull d; asm("mov.b64 %0,{%1,%1};" : "=l"(d) : "f"(x)); return d;
}
__device__ __forceinline__ ull f2pack(float x, float y) {
    ull d; asm("mov.b64 %0,{%1,%2};" : "=l"(d) : "f"(x), "f"(y)); return d;
}
__device__ __forceinline__ float2 f2unpack(ull a) {
    float lo, hi; asm("mov.b64 {%0,%1},%2;" : "=f"(lo), "=f"(hi) : "l"(a));
    return make_float2(lo, hi);
}

/* one projection output channel s: dot(W[s,:], x) + b[s], c-pair packed,
   4 short accumulator chains, x register-resident. */
#define PROJ_S(CW, CB, sIdx, val) {                                          \
    ull pa0=0ULL, pa1=0ULL, pa2=0ULL, pa3=0ULL;                              \
    _Pragma("unroll")                                                        \
    for (int t = 0; t < 16; t += 2) {                                        \
        const ulonglong2 wA = *(const ulonglong2*)&CW[(sIdx)*C_ + 4*t];      \
        pa0 = f2fma(wA.x, x2[2*t],   pa0);                                   \
        pa1 = f2fma(wA.y, x2[2*t+1], pa1);                                   \
        const ulonglong2 wB = *(const ulonglong2*)&CW[(sIdx)*C_ + 4*t + 4];  \
        pa2 = f2fma(wB.x, x2[2*t+2], pa2);                                   \
        pa3 = f2fma(wB.y, x2[2*t+3], pa3);                                   \
    }                                                                        \
    const float2 pp = f2unpack(f2add(f2add(pa0,pa2), f2add(pa1,pa3)));       \
    val = pp.x + pp.y + CB[sIdx];                                            \
}

__global__ void __launch_bounds__(128, 3)
attn_fused_kernel(const float* __restrict__ x, float* __restrict__ out)
{
    extern __shared__ float sm[];
    const int tid = threadIdx.x;
    const int bx  = blockIdx.x;
    const int wt  = bx & 15;
    const int h   = (bx >> 4) & 63;
    const int b   = bx >> 10;
    const int w0  = wt * TW;
    const int xbase = b*C_*DHW_ + h*64 + w0;

    /* ---- stage x tile: [w][d][c-contig] ---- */
    for (int e = tid; e < C_*D_*TW; e += 128) {
        const int w = e & 3;
        const int d = (e >> 2) & 31;
        const int c = e >> 7;
        sm[OFF_R1 + w*PIXST + d*XROW + c] = x[xbase + c*DHW_ + d*HW_ + w];
    }
    __syncthreads();

    const int warp = tid >> 5;    /* pixel */
    const int lane = tid & 31;    /* d (and j) */

    /* ---- x fully into registers (16 LDS.128, conflict-free) ---- */
    ull x2[32];
    {
        const float* xr = sm + OFF_R1 + warp*PIXST + lane*XROW;
#pragma unroll
        for (int t = 0; t < 16; t++) {
            const ulonglong2 v = *(const ulonglong2*)&xr[4*t];
            x2[2*t] = v.x; x2[2*t+1] = v.y;
        }
    }

    float* kT = sm + OFF_SC + warp*SCW;        /* kT[i][s], stride 36 */
    float* vS = kT + 1152;                     /* vS[sp][2i], stride 68 */

    /* ---- fused K/Q/V projections: 6 independent chains per iteration ---- */
    ull q2[SP_];
#pragma unroll 2
    for (int sp = 0; sp < SP_; sp++) {
        float k0, k1, q0, q1, v0, v1;
        PROJ_S(cWK, cBK, 2*sp,   k0);
        PROJ_S(cWQ, cBQ, 2*sp,   q0);
        PROJ_S(cWV, cBV, 2*sp,   v0);
        PROJ_S(cWK, cBK, 2*sp+1, k1);
        PROJ_S(cWQ, cBQ, 2*sp+1, q1);
        PROJ_S(cWV, cBV, 2*sp+1, v1);
        *(ull*)&kT[lane*36 + 2*sp] = f2pack(k0, k1);
        *(ull*)&vS[sp*68 + 2*lane] = f2pack(v0, v1);
        q2[sp] = f2pack(q0, q1);
    }
    __syncwarp();

    /* ---- scores[i][j=lane] ---- */
    float a[D_];
#pragma unroll
    for (int i = 0; i < D_; i++) {
        ull a0 = 0ULL, a1 = 0ULL;
#pragma unroll
        for (int t = 0; t < 8; t++) {
            const ulonglong2 kk = *(const ulonglong2*)&kT[i*36 + 4*t];
            a0 = f2fma(kk.x, q2[2*t],   a0);
            a1 = f2fma(kk.y, q2[2*t+1], a1);
        }
        const float2 p = f2unpack(f2add(a0, a1));
        a[i] = (p.x + p.y) * 0.17677669529663687f;   /* 1/sqrt(32) */
    }

    /* ---- softmax over i ---- */
    {
        float m = a[0];
#pragma unroll
        for (int i = 1; i < D_; i++) m = fmaxf(m, a[i]);
        float ssum = 0.f;
#pragma unroll
        for (int i = 0; i < D_; i++) { a[i] = __expf(a[i] - m); ssum += a[i]; }
        const float inv = 1.0f / ssum;
#pragma unroll
        for (int i = 0; i < D_; i++) a[i] *= inv;
    }

    /* ---- o2[sp] = sum_i vS(sp,i) * a[i] (dup a on the fly) ---- */
    ull o2[SP_];
#pragma unroll
    for (int sp = 0; sp < SP_; sp++) o2[sp] = 0ULL;
#pragma unroll
    for (int t = 0; t < 16; t++) {
        const ull d0 = f2dup(a[2*t]);
        const ull d1 = f2dup(a[2*t+1]);
#pragma unroll
        for (int sp = 0; sp < SP_; sp++) {
            const ulonglong2 vv = *(const ulonglong2*)&vS[sp*68 + 4*t];
            o2[sp] = f2fma(vv.x, d0, o2[sp]);
            o2[sp] = f2fma(vv.y, d1, o2[sp]);
        }
    }
    __syncthreads();   /* x-tile fully consumed -> otile overlay */

    /* ---- outproj (LDC Wo) -> otile[(c*4+warp)][lane] ---- */
#pragma unroll 8
    for (int c = 0; c < C_; c++) {
        ull a0 = 0ULL, a1 = 0ULL;
#pragma unroll
        for (int t = 0; t < 8; t++) {
            const ulonglong2 ww = *(const ulonglong2*)&cWO[c*S_ + 4*t];
            a0 = f2fma(ww.x, o2[2*t],   a0);
            a1 = f2fma(ww.y, o2[2*t+1], a1);
        }
        const float2 p = f2unpack(f2add(a0, a1));
        sm[OFF_R1 + (c*TW + warp)*OROW + lane] = p.x + p.y + cBO[c];
    }
    __syncthreads();

    /* ---- final: out = otile + residual (x re-read from global) ---- */
    for (int e = tid; e < C_*D_; e += 128) {
        const int d = e & 31;
        const int c = e >> 5;
        const float4 xv = *(const float4*)&x[xbase + c*DHW_ + d*HW_];
        float4 r;
        r.x = xv.x + sm[OFF_R1 + (c*TW + 0)*OROW + d];
        r.y = xv.y + sm[OFF_R1 + (c*TW + 1)*OROW + d];
        r.z = xv.z + sm[OFF_R1 + (c*TW + 2)*OROW + d];
        r.w = xv.w + sm[OFF_R1 + (c*TW + 3)*OROW + d];
        *(float4*)&out[xbase + c*DHW_ + d*HW_] = r;
    }
}

extern "C" void kernel_launch(void* const* d_in, const int* in_sizes, int n_in,
                              void* d_out, int out_size)
{
    const float* x = (const float*)d_in[0];
    float* out = (float*)d_out;

    cudaMemcpyToSymbolAsync(cWK, d_in[1], S_*C_*sizeof(float), 0, cudaMemcpyDeviceToDevice, 0);
    cudaMemcpyToSymbolAsync(cBK, d_in[2], S_*sizeof(float),    0, cudaMemcpyDeviceToDevice, 0);
    cudaMemcpyToSymbolAsync(cWQ, d_in[3], S_*C_*sizeof(float), 0, cudaMemcpyDeviceToDevice, 0);
    cudaMemcpyToSymbolAsync(cBQ, d_in[4], S_*sizeof(float),    0, cudaMemcpyDeviceToDevice, 0);
    cudaMemcpyToSymbolAsync(cWV, d_in[5], S_*C_*sizeof(float), 0, cudaMemcpyDeviceToDevice, 0);
    cudaMemcpyToSymbolAsync(cBV, d_in[6], S_*sizeof(float),    0, cudaMemcpyDeviceToDevice, 0);
    cudaMemcpyToSymbolAsync(cWO, d_in[7], C_*S_*sizeof(float), 0, cudaMemcpyDeviceToDevice, 0);
    cudaMemcpyToSymbolAsync(cBO, d_in[8], C_*sizeof(float),    0, cudaMemcpyDeviceToDevice, 0);

    const size_t smem_bytes = (size_t)SMEM_FLOATS * sizeof(float);
    cudaFuncSetAttribute(attn_fused_kernel,
                         cudaFuncAttributeMaxDynamicSharedMemorySize,
                         (int)smem_bytes);

    const int grid = 4 * 64 * 16;   /* B * H * (W/TW) = 4096 */
    attn_fused_kernel<<<grid, 128, smem_bytes>>>(x, out);
}

// round 17
// speedup vs baseline: 1.3186x; 1.2859x over previous
#include <cuda_runtime.h>

typedef unsigned long long ull;

#define C_ 64
#define S_ 32
#define D_ 32
#define HW_ 4096
#define DHW_ 131072
#define NCH 96

/* intermediate: [b][dhw-col][96ch], ch: 0-31 k, 32-63 q, 64-95 v */
__device__ float g_kqv[4 * DHW_ * NCH];

__constant__ float cBcat[NCH];
__constant__ float cWO[C_*S_];
__constant__ float cBO[C_];

__device__ __forceinline__ ull f2fma(ull a, ull b, ull c) {
    ull d; asm("fma.rn.f32x2 %0,%1,%2,%3;" : "=l"(d) : "l"(a), "l"(b), "l"(c)); return d;
}
__device__ __forceinline__ ull f2add(ull a, ull b) {
    ull d; asm("add.rn.f32x2 %0,%1,%2;" : "=l"(d) : "l"(a), "l"(b)); return d;
}
__device__ __forceinline__ ull f2dup(float x) {
    ull d; asm("mov.b64 %0,{%1,%1};" : "=l"(d) : "f"(x)); return d;
}
__device__ __forceinline__ ull f2pack(float x, float y) {
    ull d; asm("mov.b64 %0,{%1,%2};" : "=l"(d) : "f"(x), "f"(y)); return d;
}
__device__ __forceinline__ float2 f2unpack(ull a) {
    float lo, hi; asm("mov.b64 {%0,%1},%2;" : "=f"(lo), "=f"(hi) : "l"(a));
    return make_float2(lo, hi);
}
__device__ __forceinline__ float hadd(ull a) {
    const float2 p = f2unpack(a); return p.x + p.y;
}

/* ================= Kernel 1: KQV projection GEMM =================
   g_kqv[b][col][96] = Wcat[96,64] @ x[b][64,col] + bias.
   192 thr, tile [96ch x 128col], thread 8ch(4 pairs) x 8col. */
#define XS_STR 132
#define WT_STR 100
#define K1_SMEM_FLOATS (64*XS_STR + 64*WT_STR)   /* 14848 fl = 59392 B */

__global__ void __launch_bounds__(192, 3)
kqv_gemm_kernel(const float* __restrict__ x,
                const float* __restrict__ Wk,
                const float* __restrict__ Wq,
                const float* __restrict__ Wv)
{
    extern __shared__ float sm[];
    float* XS = sm;                   /* [k=64][132] */
    float* WT = sm + 64*XS_STR;       /* [k=64][100], ch-major */

    const int tid  = threadIdx.x;
    const int bx   = blockIdx.x;
    const int tile = bx & 1023;
    const int b    = bx >> 10;
    const int colbase = tile * 128;

    /* stage weights transposed: WT[c][ch] */
    for (int i = tid; i < S_*C_; i += 192) {
        const int c = i & 63, s = i >> 6;
        WT[c*WT_STR + s]      = Wk[i];
        WT[c*WT_STR + 32 + s] = Wq[i];
        WT[c*WT_STR + 64 + s] = Wv[i];
    }
    /* stage X[64][128] (coalesced float4) */
    for (int f = tid; f < 64*32; f += 192) {
        const int c = f >> 5;
        const int col4 = (f & 31) * 4;
        *(float4*)&XS[c*XS_STR + col4] =
            *(const float4*)&x[(size_t)(b*64 + c)*DHW_ + colbase + col4];
    }
    __syncthreads();

    const int tm = tid / 16;          /* 0..11: ch-group of 8 */
    const int tc = tid % 16;          /* 0..15: col-group of 8 */
    const int ch0  = tm * 8;
    const int col0 = tc * 8;

    /* acc[cp][col]: ch-pair (ch0+2cp, ch0+2cp+1) for column col0+col */
    ull acc[4][8];
#pragma unroll
    for (int cp = 0; cp < 4; cp++)
#pragma unroll
        for (int n = 0; n < 8; n++) acc[cp][n] = 0ULL;

#pragma unroll 4
    for (int k = 0; k < 64; k++) {
        const ulonglong2 wa = *(const ulonglong2*)&WT[k*WT_STR + ch0];      /* cp 0,1 */
        const ulonglong2 wb = *(const ulonglong2*)&WT[k*WT_STR + ch0 + 4];  /* cp 2,3 */
        const ulonglong2 xa = *(const ulonglong2*)&XS[k*XS_STR + col0];
        const ulonglong2 xb = *(const ulonglong2*)&XS[k*XS_STR + col0 + 4];
        ull xd[8];
        { float2 p;
          p = f2unpack(xa.x); xd[0]=f2dup(p.x); xd[1]=f2dup(p.y);
          p = f2unpack(xa.y); xd[2]=f2dup(p.x); xd[3]=f2dup(p.y);
          p = f2unpack(xb.x); xd[4]=f2dup(p.x); xd[5]=f2dup(p.y);
          p = f2unpack(xb.y); xd[6]=f2dup(p.x); xd[7]=f2dup(p.y); }
#pragma unroll
        for (int n = 0; n < 8; n++) {
            acc[0][n] = f2fma(wa.x, xd[n], acc[0][n]);
            acc[1][n] = f2fma(wa.y, xd[n], acc[1][n]);
            acc[2][n] = f2fma(wb.x, xd[n], acc[2][n]);
            acc[3][n] = f2fma(wb.y, xd[n], acc[3][n]);
        }
    }

    /* epilogue: +bias, write [col][ch] rows: 2 x STG.128 per column */
    const ull bb0 = *(const ull*)&cBcat[ch0];
    const ull bb1 = *(const ull*)&cBcat[ch0 + 2];
    const ull bb2 = *(const ull*)&cBcat[ch0 + 4];
    const ull bb3 = *(const ull*)&cBcat[ch0 + 6];
#pragma unroll
    for (int n = 0; n < 8; n++) {
        float* dst = &g_kqv[((size_t)b*DHW_ + colbase + col0 + n)*NCH + ch0];
        ulonglong2 r0, r1;
        r0.x = f2add(acc[0][n], bb0); r0.y = f2add(acc[1][n], bb1);
        r1.x = f2add(acc[2][n], bb2); r1.y = f2add(acc[3][n], bb3);
        *(ulonglong2*)dst       = r0;
        *(ulonglong2*)(dst + 4) = r1;
    }
}

/* ================= Kernel 2: attention + outproj + residual =================
   8 pixels/block (one h, 8 w), 256 thr, warp = pixel, lane = d (= j). */
#define OFF_KT 0          /* kT[w][d][s]: w*1156 + d*36 + s */
#define OFF_QT 9248       /* qT[w][d][s]: same shape */
#define OFF_VS 18496      /* vS[w][sp][2i]: w*1092 + sp*68 + 2i */
#define K2_SMEM_FLOATS (OFF_VS + 8*1092)   /* 27232 fl = 108928 B -> 2 CTAs */
#define OT_STR 33         /* otile (c*8+w)*33 + d, overlays [0,16896) */

__global__ void __launch_bounds__(256, 2)
attn_kernel(const float* __restrict__ x, float* __restrict__ out)
{
    extern __shared__ float sm[];
    const int tid = threadIdx.x;
    const int bx  = blockIdx.x;
    const int wt  = bx & 7;
    const int h   = (bx >> 3) & 63;
    const int b   = bx >> 9;
    const int hw0 = h*64 + wt*8;

    /* ---- stage slab: 256 rows (d,w) x 96 ch, fully coalesced ---- */
#pragma unroll 4
    for (int it = 0; it < 24; it++) {
        const int f = it*256 + tid;          /* float4 index, 6144 total */
        const int row = f / 24;              /* (d*8 + w) */
        const int c4  = f - row*24;
        const int d = row >> 3;
        const int w = row & 7;
        const float4 v = *(const float4*)
            &g_kqv[((size_t)b*DHW_ + d*4096 + hw0 + w)*NCH + c4*4];
        const int ch0 = c4*4;
        if (ch0 < 32) {
            *(float4*)&sm[OFF_KT + w*1156 + d*36 + ch0] = v;
        } else if (ch0 < 64) {
            *(float4*)&sm[OFF_QT + w*1156 + d*36 + (ch0-32)] = v;
        } else {
            const int s0 = ch0 - 64;
            const int sp0 = s0 >> 1;
            float* vb = sm + OFF_VS + w*1092 + 2*d;
            *(ull*)&vb[sp0*68]     = f2pack(v.x, v.y);
            *(ull*)&vb[(sp0+1)*68] = f2pack(v.z, v.w);
        }
    }
    __syncthreads();

    const int warp = tid >> 5;    /* pixel */
    const int lane = tid & 31;    /* d (and j) */
    const float* kT = sm + OFF_KT + warp*1156;
    const float* qT = sm + OFF_QT + warp*1156;
    const float* vS = sm + OFF_VS + warp*1092;

    /* q2[t] = (q[2t][j], q[2t+1][j]) */
    ull q2[16];
#pragma unroll
    for (int t = 0; t < 8; t++) {
        const ulonglong2 qq = *(const ulonglong2*)&qT[lane*36 + 4*t];
        q2[2*t] = qq.x; q2[2*t+1] = qq.y;
    }

    /* scores a[i] (kT reads broadcast) */
    float a[D_];
#pragma unroll
    for (int i = 0; i < D_; i++) {
        ull a0 = 0ULL, a1 = 0ULL;
#pragma unroll
        for (int t = 0; t < 8; t++) {
            const ulonglong2 kk = *(const ulonglong2*)&kT[i*36 + 4*t];
            a0 = f2fma(kk.x, q2[2*t],   a0);
            a1 = f2fma(kk.y, q2[2*t+1], a1);
        }
        a[i] = hadd(f2add(a0, a1)) * 0.17677669529663687f;   /* 1/sqrt(32) */
    }

    /* softmax over i */
    {
        float m = a[0];
#pragma unroll
        for (int i = 1; i < D_; i++) m = fmaxf(m, a[i]);
        float ssum = 0.f;
#pragma unroll
        for (int i = 0; i < D_; i++) { a[i] = __expf(a[i] - m); ssum += a[i]; }
        const float inv = 1.0f / ssum;
#pragma unroll
        for (int i = 0; i < D_; i++) a[i] *= inv;
    }

    /* o2[sp] = sum_i vS(sp,i) * a[i] (vS reads broadcast) */
    ull o2[16];
#pragma unroll
    for (int sp = 0; sp < 16; sp++) o2[sp] = 0ULL;
#pragma unroll
    for (int t = 0; t < 16; t++) {
        const ull d0 = f2dup(a[2*t]);
        const ull d1 = f2dup(a[2*t+1]);
#pragma unroll
        for (int sp = 0; sp < 16; sp++) {
            const ulonglong2 vv = *(const ulonglong2*)&vS[sp*68 + 4*t];
            o2[sp] = f2fma(vv.x, d0, o2[sp]);
            o2[sp] = f2fma(vv.y, d1, o2[sp]);
        }
    }
    __syncthreads();   /* kT/qT reads done -> region becomes otile */

    /* outproj (LDC Wo) -> otile[(c*8+warp)*33 + lane] */
#pragma unroll 8
    for (int c = 0; c < C_; c++) {
        ull a0 = 0ULL, a1 = 0ULL;
#pragma unroll
        for (int t = 0; t < 8; t++) {
            const ulonglong2 ww = *(const ulonglong2*)&cWO[c*S_ + 4*t];
            a0 = f2fma(ww.x, o2[2*t],   a0);
            a1 = f2fma(ww.y, o2[2*t+1], a1);
        }
        sm[(c*8 + warp)*OT_STR + lane] = hadd(f2add(a0, a1)) + cBO[c];
    }
    __syncthreads();

    /* final: out = otile + residual (x re-read, coalesced) */
#pragma unroll
    for (int it = 0; it < 8; it++) {
        const int row = it*256 + tid;
        const int d = row & 31;
        const int c = row >> 5;
        const float* xs = &x[(size_t)((b*64 + c)*32 + d)*4096 + hw0];
        const float4 xa = *(const float4*)xs;
        const float4 xb = *(const float4*)(xs + 4);
        float4 ra, rb;
        ra.x = xa.x + sm[(c*8 + 0)*OT_STR + d];
        ra.y = xa.y + sm[(c*8 + 1)*OT_STR + d];
        ra.z = xa.z + sm[(c*8 + 2)*OT_STR + d];
        ra.w = xa.w + sm[(c*8 + 3)*OT_STR + d];
        rb.x = xb.x + sm[(c*8 + 4)*OT_STR + d];
        rb.y = xb.y + sm[(c*8 + 5)*OT_STR + d];
        rb.z = xb.z + sm[(c*8 + 6)*OT_STR + d];
        rb.w = xb.w + sm[(c*8 + 7)*OT_STR + d];
        float* dst = &out[(size_t)((b*64 + c)*32 + d)*4096 + hw0];
        *(float4*)dst       = ra;
        *(float4*)(dst + 4) = rb;
    }
}

extern "C" void kernel_launch(void* const* d_in, const int* in_sizes, int n_in,
                              void* d_out, int out_size)
{
    const float* x  = (const float*)d_in[0];
    const float* Wk = (const float*)d_in[1];
    const float* Wq = (const float*)d_in[3];
    const float* Wv = (const float*)d_in[5];
    float* out = (float*)d_out;

    cudaMemcpyToSymbolAsync(cBcat, d_in[2], S_*sizeof(float),  0,               cudaMemcpyDeviceToDevice, 0);
    cudaMemcpyToSymbolAsync(cBcat, d_in[4], S_*sizeof(float), 32*sizeof(float), cudaMemcpyDeviceToDevice, 0);
    cudaMemcpyToSymbolAsync(cBcat, d_in[6], S_*sizeof(float), 64*sizeof(float), cudaMemcpyDeviceToDevice, 0);
    cudaMemcpyToSymbolAsync(cWO,  d_in[7], C_*S_*sizeof(float), 0, cudaMemcpyDeviceToDevice, 0);
    cudaMemcpyToSymbolAsync(cBO,  d_in[8], C_*sizeof(float),    0, cudaMemcpyDeviceToDevice, 0);

    const size_t s1 = (size_t)K1_SMEM_FLOATS * sizeof(float);
    const size_t s2 = (size_t)K2_SMEM_FLOATS * sizeof(float);
    cudaFuncSetAttribute(kqv_gemm_kernel, cudaFuncAttributeMaxDynamicSharedMemorySize, (int)s1);
    cudaFuncSetAttribute(attn_kernel,     cudaFuncAttributeMaxDynamicSharedMemorySize, (int)s2);

    kqv_gemm_kernel<<<4096, 192, s1>>>(x, Wk, Wq, Wv);
    attn_kernel<<<2048, 256, s2>>>(x, out);
}